// round 1
// baseline (speedup 1.0000x reference)
#include <cuda_runtime.h>
#include <cuda_bf16.h>

// Problem constants
#define S_LEN 4096
#define D_MODEL 768
#define NHEAD 12
#define WHEAD 64
#define N_QKV 2304   // 3*D

// ---------------- scratch (no allocations allowed) ----------------
// Q/K/V in head-major layout: [H][S][W]  (12 * 4096 * 64 floats each)
__device__ float g_q[NHEAD * S_LEN * WHEAD];
__device__ float g_k[NHEAD * S_LEN * WHEAD];
__device__ float g_v[NHEAD * S_LEN * WHEAD];

// ---------------- Kernel 1: fused QKV GEMM ----------------
// C = X[4096,768] @ W[768,2304] + b ; scattered into g_q/g_k/g_v head-major.
// BM=BN=64, BK=16, 256 threads, 4x4 per thread.
#define GP 68  // smem pitch (floats), %4==0 for float4, 68%32=4 kills transpose conflicts

__global__ __launch_bounds__(256) void qkv_gemm_kernel(
    const float* __restrict__ X, const float* __restrict__ Wq,
    const float* __restrict__ bq)
{
    __shared__ float As[16 * GP];  // As[k][m]
    __shared__ float Bs[16 * GP];  // Bs[k][n]

    const int tid = threadIdx.x;
    const int tx = tid & 15;        // n sub-tile
    const int ty = tid >> 4;        // m sub-tile
    const int n0 = blockIdx.x * 64;
    const int m0 = blockIdx.y * 64;

    float acc[4][4] = {};

    const int rowA = tid >> 2, c4A = tid & 3;      // A tile: 64 rows x 4 float4
    const int rowB = tid >> 4, c4B = tid & 15;     // B tile: 16 rows x 16 float4

    for (int k0 = 0; k0 < D_MODEL; k0 += 16) {
        // load A (64x16) transposed into As[k][m]
        float4 a = *(const float4*)&X[(size_t)(m0 + rowA) * D_MODEL + k0 + c4A * 4];
        As[(c4A * 4 + 0) * GP + rowA] = a.x;
        As[(c4A * 4 + 1) * GP + rowA] = a.y;
        As[(c4A * 4 + 2) * GP + rowA] = a.z;
        As[(c4A * 4 + 3) * GP + rowA] = a.w;
        // load B (16x64) natural into Bs[k][n]
        float4 bb = *(const float4*)&Wq[(size_t)(k0 + rowB) * N_QKV + n0 + c4B * 4];
        *(float4*)&Bs[rowB * GP + c4B * 4] = bb;
        __syncthreads();

#pragma unroll
        for (int k = 0; k < 16; ++k) {
            float4 av = *(const float4*)&As[k * GP + ty * 4];
            float4 bv = *(const float4*)&Bs[k * GP + tx * 4];
            const float ar[4] = {av.x, av.y, av.z, av.w};
            const float br[4] = {bv.x, bv.y, bv.z, bv.w};
#pragma unroll
            for (int r = 0; r < 4; ++r)
#pragma unroll
                for (int c = 0; c < 4; ++c)
                    acc[r][c] = fmaf(ar[r], br[c], acc[r][c]);
        }
        __syncthreads();
    }

    // epilogue: bias + scatter to head-major q/k/v
    const int sel = n0 / D_MODEL;           // 0=q,1=k,2=v (BN=64 divides 768)
    const int head = (n0 % D_MODEL) / WHEAD;
    float* dst = (sel == 0) ? g_q : (sel == 1) ? g_k : g_v;

#pragma unroll
    for (int r = 0; r < 4; ++r) {
        const int m = m0 + ty * 4 + r;
#pragma unroll
        for (int c = 0; c < 4; ++c) {
            const int w = tx * 4 + c;
            float val = acc[r][c] + bq[n0 + w];
            dst[((size_t)head * S_LEN + m) * WHEAD + w] = val;
        }
    }
}

// ---------------- Kernel 2: flash attention ----------------
// grid = (S/64, H), 256 threads. BR=BC=64. Online softmax.
#define AP 68          // pitch for transposed tiles
#define VP 64          // pitch for V (natural layout)
// smem floats: Qt(64*68) + Kt(64*68) + Pt(64*68) + Vs(64*64) + am(64)
#define ATTN_SMEM_FLOATS (3 * 64 * AP + 64 * VP + 64)
#define ATTN_SMEM_BYTES (ATTN_SMEM_FLOATS * 4)

__global__ __launch_bounds__(256) void attn_kernel(
    const float* __restrict__ mask, float* __restrict__ out)
{
    extern __shared__ float sm[];
    float* Qt = sm;                       // Qt[w][i]
    float* Kt = Qt + 64 * AP;             // Kt[w][j]
    float* Pt = Kt + 64 * AP;             // Pt[j][i]
    float* Vs = Pt + 64 * AP;             // Vs[j][w]
    float* am = Vs + 64 * VP;             // additive mask per kv col

    const int tid = threadIdx.x;
    const int tx = tid & 15;              // output col group (v-dim / kv-col dim)
    const int ty = tid >> 4;              // row group
    const int r0 = blockIdx.x * 64;
    const int head = blockIdx.y;

    const float* qh = g_q + (size_t)head * S_LEN * WHEAD;
    const float* kh = g_k + (size_t)head * S_LEN * WHEAD;
    const float* vh = g_v + (size_t)head * S_LEN * WHEAD;

    // ---- load Q tile (64 rows x 64 w), transposed into Qt[w][i] ----
#pragma unroll
    for (int rep = 0; rep < 4; ++rep) {
        int lin = tid + rep * 256;        // 1024 float4 total
        int i = lin >> 4;                 // row 0..63
        int w4 = lin & 15;                // float4 index along w
        float4 qv = *(const float4*)&qh[(size_t)(r0 + i) * WHEAD + w4 * 4];
        Qt[(w4 * 4 + 0) * AP + i] = qv.x;
        Qt[(w4 * 4 + 1) * AP + i] = qv.y;
        Qt[(w4 * 4 + 2) * AP + i] = qv.z;
        Qt[(w4 * 4 + 3) * AP + i] = qv.w;
    }

    float o[4][4] = {};
    float mrow[4], lrow[4];
#pragma unroll
    for (int r = 0; r < 4; ++r) { mrow[r] = -1e30f; lrow[r] = 0.0f; }

    for (int t = 0; t < S_LEN / 64; ++t) {
        const int t0 = t * 64;
        // ---- load K tile transposed, V tile natural, mask ----
#pragma unroll
        for (int rep = 0; rep < 4; ++rep) {
            int lin = tid + rep * 256;
            int j = lin >> 4;
            int w4 = lin & 15;
            float4 kv = *(const float4*)&kh[(size_t)(t0 + j) * WHEAD + w4 * 4];
            Kt[(w4 * 4 + 0) * AP + j] = kv.x;
            Kt[(w4 * 4 + 1) * AP + j] = kv.y;
            Kt[(w4 * 4 + 2) * AP + j] = kv.z;
            Kt[(w4 * 4 + 3) * AP + j] = kv.w;
            float4 vv = *(const float4*)&vh[(size_t)(t0 + j) * WHEAD + w4 * 4];
            *(float4*)&Vs[j * VP + w4 * 4] = vv;
        }
        if (tid < 64) am[tid] = -10000.0f * (1.0f - mask[t0 + tid]);
        __syncthreads();

        // ---- S = Q K^T (this thread: rows ty*4.., cols tx*4..) ----
        float s[4][4] = {};
#pragma unroll
        for (int w = 0; w < 64; ++w) {
            float4 qv = *(const float4*)&Qt[w * AP + ty * 4];
            float4 kv = *(const float4*)&Kt[w * AP + tx * 4];
            const float qr[4] = {qv.x, qv.y, qv.z, qv.w};
            const float kr[4] = {kv.x, kv.y, kv.z, kv.w};
#pragma unroll
            for (int r = 0; r < 4; ++r)
#pragma unroll
                for (int c = 0; c < 4; ++c)
                    s[r][c] = fmaf(qr[r], kr[c], s[r][c]);
        }
        // scale + additive mask
#pragma unroll
        for (int r = 0; r < 4; ++r)
#pragma unroll
            for (int c = 0; c < 4; ++c)
                s[r][c] = s[r][c] * 0.125f + am[tx * 4 + c];

        // ---- online softmax update (per row, redundant across 16 lanes) ----
#pragma unroll
        for (int r = 0; r < 4; ++r) {
            float mx = fmaxf(fmaxf(s[r][0], s[r][1]), fmaxf(s[r][2], s[r][3]));
#pragma unroll
            for (int off = 8; off; off >>= 1)
                mx = fmaxf(mx, __shfl_xor_sync(0xffffffffu, mx, off));
            float mnew = fmaxf(mrow[r], mx);
            float corr = __expf(mrow[r] - mnew);   // first tile: exp(-1e30-x)=0, no NaN
            float rs = 0.0f;
#pragma unroll
            for (int c = 0; c < 4; ++c) {
                float p = __expf(s[r][c] - mnew);
                s[r][c] = p;
                rs += p;
            }
#pragma unroll
            for (int off = 8; off; off >>= 1)
                rs += __shfl_xor_sync(0xffffffffu, rs, off);
            lrow[r] = lrow[r] * corr + rs;
            mrow[r] = mnew;
#pragma unroll
            for (int c = 0; c < 4; ++c) o[r][c] *= corr;
        }

        // ---- store P transposed: Pt[j][i] ----
#pragma unroll
        for (int c = 0; c < 4; ++c) {
            float4 pv = make_float4(s[0][c], s[1][c], s[2][c], s[3][c]);
            *(float4*)&Pt[(tx * 4 + c) * AP + ty * 4] = pv;
        }
        __syncthreads();

        // ---- O += P V ----
#pragma unroll 8
        for (int j = 0; j < 64; ++j) {
            float4 pv = *(const float4*)&Pt[j * AP + ty * 4];
            float4 vv = *(const float4*)&Vs[j * VP + tx * 4];
            const float pr[4] = {pv.x, pv.y, pv.z, pv.w};
            const float vr[4] = {vv.x, vv.y, vv.z, vv.w};
#pragma unroll
            for (int r = 0; r < 4; ++r)
#pragma unroll
                for (int c = 0; c < 4; ++c)
                    o[r][c] = fmaf(pr[r], vr[c], o[r][c]);
        }
        __syncthreads();   // before next tile overwrites Kt/Vs/Pt
    }

    // ---- epilogue: normalize and write merged-head output (B,S,D) ----
#pragma unroll
    for (int r = 0; r < 4; ++r) {
        float inv = 1.0f / lrow[r];
        const int srow = r0 + ty * 4 + r;
#pragma unroll
        for (int c = 0; c < 4; ++c) {
            const int w = tx * 4 + c;
            out[(size_t)srow * D_MODEL + head * WHEAD + w] = o[r][c] * inv;
        }
    }
}

// ---------------- launch ----------------
extern "C" void kernel_launch(void* const* d_in, const int* in_sizes, int n_in,
                              void* d_out, int out_size)
{
    const float* x    = (const float*)d_in[0];   // (1,4096,768)
    const float* mask = (const float*)d_in[1];   // (1,4096)
    const float* Wq   = (const float*)d_in[2];   // (768,2304)
    const float* bq   = (const float*)d_in[3];   // (2304,)
    float* out = (float*)d_out;                  // (1,4096,768)

    dim3 gGemm(N_QKV / 64, S_LEN / 64);          // (36, 64)
    qkv_gemm_kernel<<<gGemm, 256>>>(x, Wq, bq);

    cudaFuncSetAttribute(attn_kernel,
                         cudaFuncAttributeMaxDynamicSharedMemorySize,
                         ATTN_SMEM_BYTES);
    dim3 gAttn(S_LEN / 64, NHEAD);               // (64, 12)
    attn_kernel<<<gAttn, 256, ATTN_SMEM_BYTES>>>(mask, out);
}

// round 2
// speedup vs baseline: 2.9704x; 2.9704x over previous
#include <cuda_runtime.h>
#include <cuda_bf16.h>
#include <cstdint>

#define S_LEN 4096
#define D_MODEL 768
#define NHEAD 12
#define WHEAD 64
#define N_QKV 2304

// ---------------- scratch ----------------
__device__ float g_q[NHEAD * S_LEN * WHEAD];
__device__ float g_k[NHEAD * S_LEN * WHEAD];
__device__ float g_v[NHEAD * S_LEN * WHEAD];

// ---------------- helpers ----------------
__device__ __forceinline__ uint32_t f2tf32(float x) {
    uint32_t u;
    asm("cvt.rna.tf32.f32 %0, %1;" : "=r"(u) : "f"(x));
    return u;
}

__device__ __forceinline__ void mma_tf32(
    float& d0, float& d1, float& d2, float& d3,
    uint32_t a0, uint32_t a1, uint32_t a2, uint32_t a3,
    uint32_t b0, uint32_t b1)
{
    asm volatile(
        "mma.sync.aligned.m16n8k8.row.col.f32.tf32.tf32.f32 "
        "{%0,%1,%2,%3},{%4,%5,%6,%7},{%8,%9},{%0,%1,%2,%3};"
        : "+f"(d0), "+f"(d1), "+f"(d2), "+f"(d3)
        : "r"(a0), "r"(a1), "r"(a2), "r"(a3), "r"(b0), "r"(b1));
}

// XOR swizzle for the transposed K tile (q = w>>2, 0..15)
__device__ __forceinline__ int kt_swz(int q) {
    return ((q & 3) << 3) | (((q >> 2) & 3) << 1);
}

// =============== Kernel 1: QKV GEMM (tf32 tensor cores) ===============
// C[4096,2304] = X[4096,768] @ W[768,2304] + b, scattered head-major.
// Block tile 128x64, BK=32, 256 threads = 8 warps (4m x 2n),
// each warp 32x32 via 2x4 m16n8 tiles.
#define APITCH 36   // mod 32 == 4 -> conflict-free A-fragment reads
#define BPITCH 72   // mod 32 == 8 -> conflict-free B-fragment reads

__global__ __launch_bounds__(256) void qkv_gemm_tc(
    const float* __restrict__ X, const float* __restrict__ Wq,
    const float* __restrict__ bq)
{
    __shared__ uint32_t As[128 * APITCH];
    __shared__ uint32_t Bs[32 * BPITCH];

    const int tid = threadIdx.x;
    const int wid = tid >> 5;
    const int lane = tid & 31;
    const int g = lane >> 2;     // group id (row within m16)
    const int c = lane & 3;      // thread-in-group (k / col pair)
    const int warp_m = wid >> 1; // 0..3
    const int warp_n = wid & 1;  // 0..1
    const int m0 = blockIdx.y * 128;
    const int n0 = blockIdx.x * 64;

    float acc[2][4][4];
#pragma unroll
    for (int mt = 0; mt < 2; ++mt)
#pragma unroll
        for (int nt = 0; nt < 4; ++nt)
#pragma unroll
            for (int i = 0; i < 4; ++i) acc[mt][nt][i] = 0.0f;

    for (int k0 = 0; k0 < D_MODEL; k0 += 32) {
        // A tile 128x32: 1024 float4, 4 per thread
#pragma unroll
        for (int r = 0; r < 4; ++r) {
            int lin = tid + r * 256;
            int row = lin >> 3, c4 = lin & 7;
            float4 a = *(const float4*)&X[(size_t)(m0 + row) * D_MODEL + k0 + c4 * 4];
            uint4 u = make_uint4(f2tf32(a.x), f2tf32(a.y), f2tf32(a.z), f2tf32(a.w));
            *(uint4*)&As[row * APITCH + c4 * 4] = u;
        }
        // B tile 32x64: 512 float4, 2 per thread
#pragma unroll
        for (int r = 0; r < 2; ++r) {
            int lin = tid + r * 256;
            int row = lin >> 4, c4 = lin & 15;
            float4 b = *(const float4*)&Wq[(size_t)(k0 + row) * N_QKV + n0 + c4 * 4];
            uint4 u = make_uint4(f2tf32(b.x), f2tf32(b.y), f2tf32(b.z), f2tf32(b.w));
            *(uint4*)&Bs[row * BPITCH + c4 * 4] = u;
        }
        __syncthreads();

#pragma unroll
        for (int kk = 0; kk < 4; ++kk) {
            uint32_t af[2][4];
#pragma unroll
            for (int mt = 0; mt < 2; ++mt) {
                int mr = warp_m * 32 + mt * 16 + g;
                af[mt][0] = As[mr * APITCH + kk * 8 + c];
                af[mt][1] = As[(mr + 8) * APITCH + kk * 8 + c];
                af[mt][2] = As[mr * APITCH + kk * 8 + c + 4];
                af[mt][3] = As[(mr + 8) * APITCH + kk * 8 + c + 4];
            }
#pragma unroll
            for (int nt = 0; nt < 4; ++nt) {
                int nc = warp_n * 32 + nt * 8 + g;
                uint32_t b0 = Bs[(kk * 8 + c) * BPITCH + nc];
                uint32_t b1 = Bs[(kk * 8 + c + 4) * BPITCH + nc];
#pragma unroll
                for (int mt = 0; mt < 2; ++mt)
                    mma_tf32(acc[mt][nt][0], acc[mt][nt][1], acc[mt][nt][2], acc[mt][nt][3],
                             af[mt][0], af[mt][1], af[mt][2], af[mt][3], b0, b1);
            }
        }
        __syncthreads();
    }

    // epilogue: bias + scatter head-major (BN=64 lies within one q/k/v section & head)
    const int sel = n0 / D_MODEL;
    const int head = (n0 % D_MODEL) / WHEAD;
    float* dst = (sel == 0) ? g_q : (sel == 1) ? g_k : g_v;

#pragma unroll
    for (int mt = 0; mt < 2; ++mt) {
#pragma unroll
        for (int nt = 0; nt < 4; ++nt) {
            int w = warp_n * 32 + nt * 8 + 2 * c;
            float b0 = bq[n0 + w], b1 = bq[n0 + w + 1];
            int m_lo = m0 + warp_m * 32 + mt * 16 + g;
            float2 lo = make_float2(acc[mt][nt][0] + b0, acc[mt][nt][1] + b1);
            float2 hi = make_float2(acc[mt][nt][2] + b0, acc[mt][nt][3] + b1);
            *(float2*)&dst[((size_t)head * S_LEN + m_lo) * WHEAD + w] = lo;
            *(float2*)&dst[((size_t)head * S_LEN + m_lo + 8) * WHEAD + w] = hi;
        }
    }
}

// =============== Kernel 2: flash attention (tf32 tensor cores) ===============
// grid (S/64, H), 128 threads = 4 warps; each warp owns 16 query rows.
// BR=BC=64. S = Q K^T on tensor cores, register softmax, P via smem, O += P V.
#define QPITCH 68   // A-layout pitch (mod 32 == 4)
#define KPITCH 72   // B-layout pitch (mod 32 == 8)
#define PPITCH 68
#define VPITCH 72
#define SM_Q   0
#define SM_KP  (64 * QPITCH)            // K^T tile, later aliased by P
#define SM_V   (SM_KP + 64 * KPITCH)
#define SM_AM  (SM_V + 64 * VPITCH)
#define ATTN_SMEM_U32 (SM_AM + 64)
#define ATTN_SMEM_BYTES (ATTN_SMEM_U32 * 4)

__global__ __launch_bounds__(128, 4) void attn_tc(
    const float* __restrict__ mask, float* __restrict__ out)
{
    extern __shared__ uint32_t sm[];
    float* smf = (float*)sm;

    const int tid = threadIdx.x;
    const int wid = tid >> 5;      // warp: rows wid*16 .. wid*16+15
    const int lane = tid & 31;
    const int g = lane >> 2;
    const int c = lane & 3;
    const int r0 = blockIdx.x * 64;
    const int head = blockIdx.y;

    const float* qh = g_q + (size_t)head * S_LEN * WHEAD;
    const float* kh = g_k + (size_t)head * S_LEN * WHEAD;
    const float* vh = g_v + (size_t)head * S_LEN * WHEAD;

    // ---- load Q tile (64x64) as tf32, natural [row][w] ----
#pragma unroll
    for (int r = 0; r < 8; ++r) {
        int lin = tid + r * 128;
        int row = lin >> 4, c4 = lin & 15;
        float4 q4 = *(const float4*)&qh[(size_t)(r0 + row) * WHEAD + c4 * 4];
        uint4 u = make_uint4(f2tf32(q4.x), f2tf32(q4.y), f2tf32(q4.z), f2tf32(q4.w));
        *(uint4*)&sm[SM_Q + row * QPITCH + c4 * 4] = u;
    }

    float oacc[8][4];
#pragma unroll
    for (int nt = 0; nt < 8; ++nt)
#pragma unroll
        for (int i = 0; i < 4; ++i) oacc[nt][i] = 0.0f;
    float m_lo = -1e30f, m_hi = -1e30f, l_lo = 0.0f, l_hi = 0.0f;

    for (int t = 0; t < S_LEN / 64; ++t) {
        const int t0 = t * 64;
        __syncthreads();   // previous PV done reading Vs / P slab before overwrite

        // ---- load K (transposed+swizzled) and V (natural), tf32 ----
#pragma unroll
        for (int r = 0; r < 8; ++r) {
            int lin = tid + r * 128;
            int j = lin >> 4, w4 = lin & 15;
            float4 k4 = *(const float4*)&kh[(size_t)(t0 + j) * WHEAD + w4 * 4];
            int jj = j ^ kt_swz(w4);
            sm[SM_KP + (w4 * 4 + 0) * KPITCH + jj] = f2tf32(k4.x);
            sm[SM_KP + (w4 * 4 + 1) * KPITCH + jj] = f2tf32(k4.y);
            sm[SM_KP + (w4 * 4 + 2) * KPITCH + jj] = f2tf32(k4.z);
            sm[SM_KP + (w4 * 4 + 3) * KPITCH + jj] = f2tf32(k4.w);
            float4 v4 = *(const float4*)&vh[(size_t)(t0 + j) * WHEAD + w4 * 4];
            uint4 u = make_uint4(f2tf32(v4.x), f2tf32(v4.y), f2tf32(v4.z), f2tf32(v4.w));
            *(uint4*)&sm[SM_V + j * VPITCH + w4 * 4] = u;
        }
        if (tid < 64) smf[SM_AM + tid] = -10000.0f * (1.0f - mask[t0 + tid]);
        __syncthreads();

        // ---- S = Q K^T : warp computes 16x64 via 8 n-tiles, 8 k-steps ----
        float sacc[8][4];
#pragma unroll
        for (int nt = 0; nt < 8; ++nt)
#pragma unroll
            for (int i = 0; i < 4; ++i) sacc[nt][i] = 0.0f;

#pragma unroll
        for (int kk = 0; kk < 8; ++kk) {
            int mr = wid * 16 + g;
            uint32_t a0 = sm[SM_Q + mr * QPITCH + kk * 8 + c];
            uint32_t a1 = sm[SM_Q + (mr + 8) * QPITCH + kk * 8 + c];
            uint32_t a2 = sm[SM_Q + mr * QPITCH + kk * 8 + c + 4];
            uint32_t a3 = sm[SM_Q + (mr + 8) * QPITCH + kk * 8 + c + 4];
            int s0 = kt_swz(kk * 2), s1 = kt_swz(kk * 2 + 1);
#pragma unroll
            for (int nt = 0; nt < 8; ++nt) {
                uint32_t b0 = sm[SM_KP + (kk * 8 + c) * KPITCH + ((nt * 8 + g) ^ s0)];
                uint32_t b1 = sm[SM_KP + (kk * 8 + c + 4) * KPITCH + ((nt * 8 + g) ^ s1)];
                mma_tf32(sacc[nt][0], sacc[nt][1], sacc[nt][2], sacc[nt][3],
                         a0, a1, a2, a3, b0, b1);
            }
        }

        // ---- scale + mask + online softmax (rows g and g+8 of this warp) ----
        float vmax_lo = -1e30f, vmax_hi = -1e30f;
#pragma unroll
        for (int nt = 0; nt < 8; ++nt) {
            float am0 = smf[SM_AM + nt * 8 + 2 * c];
            float am1 = smf[SM_AM + nt * 8 + 2 * c + 1];
            sacc[nt][0] = sacc[nt][0] * 0.125f + am0;
            sacc[nt][1] = sacc[nt][1] * 0.125f + am1;
            sacc[nt][2] = sacc[nt][2] * 0.125f + am0;
            sacc[nt][3] = sacc[nt][3] * 0.125f + am1;
            vmax_lo = fmaxf(vmax_lo, fmaxf(sacc[nt][0], sacc[nt][1]));
            vmax_hi = fmaxf(vmax_hi, fmaxf(sacc[nt][2], sacc[nt][3]));
        }
#pragma unroll
        for (int off = 1; off <= 2; off <<= 1) {
            vmax_lo = fmaxf(vmax_lo, __shfl_xor_sync(0xffffffffu, vmax_lo, off));
            vmax_hi = fmaxf(vmax_hi, __shfl_xor_sync(0xffffffffu, vmax_hi, off));
        }
        float mn_lo = fmaxf(m_lo, vmax_lo);
        float mn_hi = fmaxf(m_hi, vmax_hi);
        float corr_lo = __expf(m_lo - mn_lo);
        float corr_hi = __expf(m_hi - mn_hi);
        float rs_lo = 0.0f, rs_hi = 0.0f;
#pragma unroll
        for (int nt = 0; nt < 8; ++nt) {
            sacc[nt][0] = __expf(sacc[nt][0] - mn_lo);
            sacc[nt][1] = __expf(sacc[nt][1] - mn_lo);
            sacc[nt][2] = __expf(sacc[nt][2] - mn_hi);
            sacc[nt][3] = __expf(sacc[nt][3] - mn_hi);
            rs_lo += sacc[nt][0] + sacc[nt][1];
            rs_hi += sacc[nt][2] + sacc[nt][3];
        }
#pragma unroll
        for (int off = 1; off <= 2; off <<= 1) {
            rs_lo += __shfl_xor_sync(0xffffffffu, rs_lo, off);
            rs_hi += __shfl_xor_sync(0xffffffffu, rs_hi, off);
        }
        l_lo = l_lo * corr_lo + rs_lo;
        l_hi = l_hi * corr_hi + rs_hi;
        m_lo = mn_lo; m_hi = mn_hi;
#pragma unroll
        for (int nt = 0; nt < 8; ++nt) {
            oacc[nt][0] *= corr_lo; oacc[nt][1] *= corr_lo;
            oacc[nt][2] *= corr_hi; oacc[nt][3] *= corr_hi;
        }

        __syncthreads();   // all warps done reading K^T before P overwrites it

        // ---- store P (tf32) into A-layout slab aliasing K^T region ----
        {
            int mr = wid * 16 + g;
#pragma unroll
            for (int nt = 0; nt < 8; ++nt) {
                uint2 lo = make_uint2(f2tf32(sacc[nt][0]), f2tf32(sacc[nt][1]));
                uint2 hi = make_uint2(f2tf32(sacc[nt][2]), f2tf32(sacc[nt][3]));
                *(uint2*)&sm[SM_KP + mr * PPITCH + nt * 8 + 2 * c] = lo;
                *(uint2*)&sm[SM_KP + (mr + 8) * PPITCH + nt * 8 + 2 * c] = hi;
            }
        }
        __syncwarp();

        // ---- O += P V ----
#pragma unroll
        for (int kk = 0; kk < 8; ++kk) {
            int mr = wid * 16 + g;
            uint32_t a0 = sm[SM_KP + mr * PPITCH + kk * 8 + c];
            uint32_t a1 = sm[SM_KP + (mr + 8) * PPITCH + kk * 8 + c];
            uint32_t a2 = sm[SM_KP + mr * PPITCH + kk * 8 + c + 4];
            uint32_t a3 = sm[SM_KP + (mr + 8) * PPITCH + kk * 8 + c + 4];
#pragma unroll
            for (int nt = 0; nt < 8; ++nt) {
                uint32_t b0 = sm[SM_V + (kk * 8 + c) * VPITCH + nt * 8 + g];
                uint32_t b1 = sm[SM_V + (kk * 8 + c + 4) * VPITCH + nt * 8 + g];
                mma_tf32(oacc[nt][0], oacc[nt][1], oacc[nt][2], oacc[nt][3],
                         a0, a1, a2, a3, b0, b1);
            }
        }
    }

    // ---- epilogue: normalize, write merged-head output ----
    float inv_lo = 1.0f / l_lo;
    float inv_hi = 1.0f / l_hi;
    int row_lo = r0 + wid * 16 + g;
#pragma unroll
    for (int nt = 0; nt < 8; ++nt) {
        int col = head * WHEAD + nt * 8 + 2 * c;
        float2 lo = make_float2(oacc[nt][0] * inv_lo, oacc[nt][1] * inv_lo);
        float2 hi = make_float2(oacc[nt][2] * inv_hi, oacc[nt][3] * inv_hi);
        *(float2*)&out[(size_t)row_lo * D_MODEL + col] = lo;
        *(float2*)&out[(size_t)(row_lo + 8) * D_MODEL + col] = hi;
    }
}

// ---------------- launch ----------------
extern "C" void kernel_launch(void* const* d_in, const int* in_sizes, int n_in,
                              void* d_out, int out_size)
{
    const float* x    = (const float*)d_in[0];
    const float* mask = (const float*)d_in[1];
    const float* Wq   = (const float*)d_in[2];
    const float* bq   = (const float*)d_in[3];
    float* out = (float*)d_out;

    dim3 gGemm(N_QKV / 64, S_LEN / 128);         // (36, 32)
    qkv_gemm_tc<<<gGemm, 256>>>(x, Wq, bq);

    cudaFuncSetAttribute(attn_tc,
                         cudaFuncAttributeMaxDynamicSharedMemorySize,
                         ATTN_SMEM_BYTES);
    dim3 gAttn(S_LEN / 64, NHEAD);               // (64, 12)
    attn_tc<<<gAttn, 128, ATTN_SMEM_BYTES>>>(mask, out);
}

// round 3
// speedup vs baseline: 3.6506x; 1.2290x over previous
#include <cuda_runtime.h>
#include <cuda_bf16.h>
#include <cstdint>

#define S_LEN 4096
#define D_MODEL 768
#define NHEAD 12
#define WHEAD 64
#define N_QKV 2304

// ---------------- scratch ----------------
__device__ float g_q[NHEAD * S_LEN * WHEAD];
__device__ float g_k[NHEAD * S_LEN * WHEAD];
__device__ float g_v[NHEAD * S_LEN * WHEAD];

// ---------------- helpers ----------------
__device__ __forceinline__ uint32_t f2tf32(float x) {
    uint32_t u;
    asm("cvt.rna.tf32.f32 %0, %1;" : "=r"(u) : "f"(x));
    return u;
}

__device__ __forceinline__ void mma_tf32(
    float& d0, float& d1, float& d2, float& d3,
    uint32_t a0, uint32_t a1, uint32_t a2, uint32_t a3,
    uint32_t b0, uint32_t b1)
{
    asm volatile(
        "mma.sync.aligned.m16n8k8.row.col.f32.tf32.tf32.f32 "
        "{%0,%1,%2,%3},{%4,%5,%6,%7},{%8,%9},{%0,%1,%2,%3};"
        : "+f"(d0), "+f"(d1), "+f"(d2), "+f"(d3)
        : "r"(a0), "r"(a1), "r"(a2), "r"(a3), "r"(b0), "r"(b1));
}

// XOR swizzle for the transposed K tile (q = w>>2, 0..15)
__device__ __forceinline__ int kt_swz(int q) {
    return ((q & 3) << 3) | (((q >> 2) & 3) << 1);
}

// =============== Kernel 1: QKV GEMM (tf32 tensor cores) ===============
#define APITCH 36
#define BPITCH 72

__global__ __launch_bounds__(256) void qkv_gemm_tc(
    const float* __restrict__ X, const float* __restrict__ Wq,
    const float* __restrict__ bq)
{
    __shared__ uint32_t As[128 * APITCH];
    __shared__ uint32_t Bs[32 * BPITCH];

    const int tid = threadIdx.x;
    const int wid = tid >> 5;
    const int lane = tid & 31;
    const int g = lane >> 2;
    const int c = lane & 3;
    const int warp_m = wid >> 1;
    const int warp_n = wid & 1;
    const int m0 = blockIdx.y * 128;
    const int n0 = blockIdx.x * 64;

    float acc[2][4][4];
#pragma unroll
    for (int mt = 0; mt < 2; ++mt)
#pragma unroll
        for (int nt = 0; nt < 4; ++nt)
#pragma unroll
            for (int i = 0; i < 4; ++i) acc[mt][nt][i] = 0.0f;

    for (int k0 = 0; k0 < D_MODEL; k0 += 32) {
#pragma unroll
        for (int r = 0; r < 4; ++r) {
            int lin = tid + r * 256;
            int row = lin >> 3, c4 = lin & 7;
            float4 a = *(const float4*)&X[(size_t)(m0 + row) * D_MODEL + k0 + c4 * 4];
            uint4 u = make_uint4(f2tf32(a.x), f2tf32(a.y), f2tf32(a.z), f2tf32(a.w));
            *(uint4*)&As[row * APITCH + c4 * 4] = u;
        }
#pragma unroll
        for (int r = 0; r < 2; ++r) {
            int lin = tid + r * 256;
            int row = lin >> 4, c4 = lin & 15;
            float4 b = *(const float4*)&Wq[(size_t)(k0 + row) * N_QKV + n0 + c4 * 4];
            uint4 u = make_uint4(f2tf32(b.x), f2tf32(b.y), f2tf32(b.z), f2tf32(b.w));
            *(uint4*)&Bs[row * BPITCH + c4 * 4] = u;
        }
        __syncthreads();

#pragma unroll
        for (int kk = 0; kk < 4; ++kk) {
            uint32_t af[2][4];
#pragma unroll
            for (int mt = 0; mt < 2; ++mt) {
                int mr = warp_m * 32 + mt * 16 + g;
                af[mt][0] = As[mr * APITCH + kk * 8 + c];
                af[mt][1] = As[(mr + 8) * APITCH + kk * 8 + c];
                af[mt][2] = As[mr * APITCH + kk * 8 + c + 4];
                af[mt][3] = As[(mr + 8) * APITCH + kk * 8 + c + 4];
            }
#pragma unroll
            for (int nt = 0; nt < 4; ++nt) {
                int nc = warp_n * 32 + nt * 8 + g;
                uint32_t b0 = Bs[(kk * 8 + c) * BPITCH + nc];
                uint32_t b1 = Bs[(kk * 8 + c + 4) * BPITCH + nc];
#pragma unroll
                for (int mt = 0; mt < 2; ++mt)
                    mma_tf32(acc[mt][nt][0], acc[mt][nt][1], acc[mt][nt][2], acc[mt][nt][3],
                             af[mt][0], af[mt][1], af[mt][2], af[mt][3], b0, b1);
            }
        }
        __syncthreads();
    }

    const int sel = n0 / D_MODEL;
    const int head = (n0 % D_MODEL) / WHEAD;
    float* dst = (sel == 0) ? g_q : (sel == 1) ? g_k : g_v;

#pragma unroll
    for (int mt = 0; mt < 2; ++mt) {
#pragma unroll
        for (int nt = 0; nt < 4; ++nt) {
            int w = warp_n * 32 + nt * 8 + 2 * c;
            float b0 = bq[n0 + w], b1 = bq[n0 + w + 1];
            int m_lo = m0 + warp_m * 32 + mt * 16 + g;
            float2 lo = make_float2(acc[mt][nt][0] + b0, acc[mt][nt][1] + b1);
            float2 hi = make_float2(acc[mt][nt][2] + b0, acc[mt][nt][3] + b1);
            *(float2*)&dst[((size_t)head * S_LEN + m_lo) * WHEAD + w] = lo;
            *(float2*)&dst[((size_t)head * S_LEN + m_lo + 8) * WHEAD + w] = hi;
        }
    }
}

// =============== Kernel 2: flash attention (tf32 tensor cores) ===============
// grid (S/128, H), 128 threads = 4 warps; each warp owns 32 query rows
// (2 m16 tiles) so K^T/V B-fragments are reused across 2 mma's.
// P never touches smem: S C-fragments are permuted into PV A-fragments
// with intra-quad shuffles.
#define QPITCH 68   // mod 32 == 4 -> conflict-free A reads
#define KPITCH 72   // mod 32 == 8 -> conflict-free B reads
#define VPITCH 72
#define SM_Q   0
#define SM_K   (128 * QPITCH)
#define SM_V   (SM_K + 64 * KPITCH)
#define SM_AM  (SM_V + 64 * VPITCH)
#define ATTN_SMEM_U32 (SM_AM + 64)
#define ATTN_SMEM_BYTES (ATTN_SMEM_U32 * 4)   // ~72 KB

__global__ __launch_bounds__(128, 3) void attn_tc(
    const float* __restrict__ mask, float* __restrict__ out)
{
    extern __shared__ uint32_t sm[];
    float* smf = (float*)sm;

    const int tid = threadIdx.x;
    const int wid = tid >> 5;
    const int lane = tid & 31;
    const int g = lane >> 2;
    const int c = lane & 3;
    const int srcA = (lane & 28) | (c >> 1);   // quad-local shuffle sources
    const int srcB = srcA + 2;
    const int r0 = blockIdx.x * 128;
    const int head = blockIdx.y;

    const float* qh = g_q + (size_t)head * S_LEN * WHEAD;
    const float* kh = g_k + (size_t)head * S_LEN * WHEAD;
    const float* vh = g_v + (size_t)head * S_LEN * WHEAD;

    // ---- load Q tile (128x64), tf32, natural [row][w] ----
#pragma unroll
    for (int r = 0; r < 16; ++r) {
        int lin = tid + r * 128;
        int row = lin >> 4, c4 = lin & 15;
        float4 q4 = *(const float4*)&qh[(size_t)(r0 + row) * WHEAD + c4 * 4];
        uint4 u = make_uint4(f2tf32(q4.x), f2tf32(q4.y), f2tf32(q4.z), f2tf32(q4.w));
        *(uint4*)&sm[SM_Q + row * QPITCH + c4 * 4] = u;
    }

    float oacc[2][8][4];
#pragma unroll
    for (int mt = 0; mt < 2; ++mt)
#pragma unroll
        for (int nt = 0; nt < 8; ++nt)
#pragma unroll
            for (int i = 0; i < 4; ++i) oacc[mt][nt][i] = 0.0f;
    float mrow[2][2], lrow[2][2];
#pragma unroll
    for (int mt = 0; mt < 2; ++mt) {
        mrow[mt][0] = mrow[mt][1] = -1e30f;
        lrow[mt][0] = lrow[mt][1] = 0.0f;
    }

    for (int t = 0; t < S_LEN / 64; ++t) {
        const int t0 = t * 64;
        __syncthreads();   // previous tile's K/V reads complete

        // ---- load K (transposed+swizzled) and V (natural), tf32 ----
#pragma unroll
        for (int r = 0; r < 8; ++r) {
            int lin = tid + r * 128;
            int j = lin >> 4, w4 = lin & 15;
            float4 k4 = *(const float4*)&kh[(size_t)(t0 + j) * WHEAD + w4 * 4];
            int jj = j ^ kt_swz(w4);
            sm[SM_K + (w4 * 4 + 0) * KPITCH + jj] = f2tf32(k4.x);
            sm[SM_K + (w4 * 4 + 1) * KPITCH + jj] = f2tf32(k4.y);
            sm[SM_K + (w4 * 4 + 2) * KPITCH + jj] = f2tf32(k4.z);
            sm[SM_K + (w4 * 4 + 3) * KPITCH + jj] = f2tf32(k4.w);
            float4 v4 = *(const float4*)&vh[(size_t)(t0 + j) * WHEAD + w4 * 4];
            uint4 u = make_uint4(f2tf32(v4.x), f2tf32(v4.y), f2tf32(v4.z), f2tf32(v4.w));
            *(uint4*)&sm[SM_V + j * VPITCH + w4 * 4] = u;
        }
        if (tid < 64) smf[SM_AM + tid] = -10000.0f * (1.0f - mask[t0 + tid]);
        __syncthreads();

        // ---- S = Q K^T : 32 rows x 64 cols per warp ----
        float sacc[2][8][4];
#pragma unroll
        for (int mt = 0; mt < 2; ++mt)
#pragma unroll
            for (int nt = 0; nt < 8; ++nt)
#pragma unroll
                for (int i = 0; i < 4; ++i) sacc[mt][nt][i] = 0.0f;

#pragma unroll
        for (int kk = 0; kk < 8; ++kk) {
            uint32_t af[2][4];
#pragma unroll
            for (int mt = 0; mt < 2; ++mt) {
                int mr = wid * 32 + mt * 16 + g;
                af[mt][0] = sm[SM_Q + mr * QPITCH + kk * 8 + c];
                af[mt][1] = sm[SM_Q + (mr + 8) * QPITCH + kk * 8 + c];
                af[mt][2] = sm[SM_Q + mr * QPITCH + kk * 8 + c + 4];
                af[mt][3] = sm[SM_Q + (mr + 8) * QPITCH + kk * 8 + c + 4];
            }
            int s0 = kt_swz(kk * 2), s1 = kt_swz(kk * 2 + 1);
#pragma unroll
            for (int nt = 0; nt < 8; ++nt) {
                uint32_t b0 = sm[SM_K + (kk * 8 + c) * KPITCH + ((nt * 8 + g) ^ s0)];
                uint32_t b1 = sm[SM_K + (kk * 8 + c + 4) * KPITCH + ((nt * 8 + g) ^ s1)];
#pragma unroll
                for (int mt = 0; mt < 2; ++mt)
                    mma_tf32(sacc[mt][nt][0], sacc[mt][nt][1], sacc[mt][nt][2], sacc[mt][nt][3],
                             af[mt][0], af[mt][1], af[mt][2], af[mt][3], b0, b1);
            }
        }

        // ---- scale + mask + online softmax per m-tile ----
#pragma unroll
        for (int mt = 0; mt < 2; ++mt) {
            float vmax_lo = -1e30f, vmax_hi = -1e30f;
#pragma unroll
            for (int nt = 0; nt < 8; ++nt) {
                float am0 = smf[SM_AM + nt * 8 + 2 * c];
                float am1 = smf[SM_AM + nt * 8 + 2 * c + 1];
                sacc[mt][nt][0] = sacc[mt][nt][0] * 0.125f + am0;
                sacc[mt][nt][1] = sacc[mt][nt][1] * 0.125f + am1;
                sacc[mt][nt][2] = sacc[mt][nt][2] * 0.125f + am0;
                sacc[mt][nt][3] = sacc[mt][nt][3] * 0.125f + am1;
                vmax_lo = fmaxf(vmax_lo, fmaxf(sacc[mt][nt][0], sacc[mt][nt][1]));
                vmax_hi = fmaxf(vmax_hi, fmaxf(sacc[mt][nt][2], sacc[mt][nt][3]));
            }
#pragma unroll
            for (int off = 1; off <= 2; off <<= 1) {
                vmax_lo = fmaxf(vmax_lo, __shfl_xor_sync(0xffffffffu, vmax_lo, off));
                vmax_hi = fmaxf(vmax_hi, __shfl_xor_sync(0xffffffffu, vmax_hi, off));
            }
            float mn_lo = fmaxf(mrow[mt][0], vmax_lo);
            float mn_hi = fmaxf(mrow[mt][1], vmax_hi);
            float corr_lo = __expf(mrow[mt][0] - mn_lo);
            float corr_hi = __expf(mrow[mt][1] - mn_hi);
            float rs_lo = 0.0f, rs_hi = 0.0f;
#pragma unroll
            for (int nt = 0; nt < 8; ++nt) {
                sacc[mt][nt][0] = __expf(sacc[mt][nt][0] - mn_lo);
                sacc[mt][nt][1] = __expf(sacc[mt][nt][1] - mn_lo);
                sacc[mt][nt][2] = __expf(sacc[mt][nt][2] - mn_hi);
                sacc[mt][nt][3] = __expf(sacc[mt][nt][3] - mn_hi);
                rs_lo += sacc[mt][nt][0] + sacc[mt][nt][1];
                rs_hi += sacc[mt][nt][2] + sacc[mt][nt][3];
            }
#pragma unroll
            for (int off = 1; off <= 2; off <<= 1) {
                rs_lo += __shfl_xor_sync(0xffffffffu, rs_lo, off);
                rs_hi += __shfl_xor_sync(0xffffffffu, rs_hi, off);
            }
            lrow[mt][0] = lrow[mt][0] * corr_lo + rs_lo;
            lrow[mt][1] = lrow[mt][1] * corr_hi + rs_hi;
            mrow[mt][0] = mn_lo; mrow[mt][1] = mn_hi;
#pragma unroll
            for (int nt = 0; nt < 8; ++nt) {
                oacc[mt][nt][0] *= corr_lo; oacc[mt][nt][1] *= corr_lo;
                oacc[mt][nt][2] *= corr_hi; oacc[mt][nt][3] *= corr_hi;
            }
        }

        // ---- convert P to tf32 in registers ----
        uint32_t su[2][8][4];
#pragma unroll
        for (int mt = 0; mt < 2; ++mt)
#pragma unroll
            for (int nt = 0; nt < 8; ++nt)
#pragma unroll
                for (int i = 0; i < 4; ++i)
                    su[mt][nt][i] = f2tf32(sacc[mt][nt][i]);

        // ---- O += P V ; P A-frags built by intra-quad shuffles ----
#pragma unroll
        for (int kk = 0; kk < 8; ++kk) {
            uint32_t af[2][4];
#pragma unroll
            for (int mt = 0; mt < 2; ++mt) {
                uint32_t p0 = su[mt][kk][0], p1 = su[mt][kk][1];
                uint32_t p2 = su[mt][kk][2], p3 = su[mt][kk][3];
                uint32_t x0 = __shfl_sync(0xffffffffu, p0, srcA);
                uint32_t x1 = __shfl_sync(0xffffffffu, p1, srcA);
                uint32_t y0 = __shfl_sync(0xffffffffu, p0, srcB);
                uint32_t y1 = __shfl_sync(0xffffffffu, p1, srcB);
                af[mt][0] = (c & 1) ? x1 : x0;
                af[mt][2] = (c & 1) ? y1 : y0;
                uint32_t x2 = __shfl_sync(0xffffffffu, p2, srcA);
                uint32_t x3 = __shfl_sync(0xffffffffu, p3, srcA);
                uint32_t y2 = __shfl_sync(0xffffffffu, p2, srcB);
                uint32_t y3 = __shfl_sync(0xffffffffu, p3, srcB);
                af[mt][1] = (c & 1) ? x3 : x2;
                af[mt][3] = (c & 1) ? y3 : y2;
            }
#pragma unroll
            for (int nt = 0; nt < 8; ++nt) {
                uint32_t b0 = sm[SM_V + (kk * 8 + c) * VPITCH + nt * 8 + g];
                uint32_t b1 = sm[SM_V + (kk * 8 + c + 4) * VPITCH + nt * 8 + g];
#pragma unroll
                for (int mt = 0; mt < 2; ++mt)
                    mma_tf32(oacc[mt][nt][0], oacc[mt][nt][1], oacc[mt][nt][2], oacc[mt][nt][3],
                             af[mt][0], af[mt][1], af[mt][2], af[mt][3], b0, b1);
            }
        }
    }

    // ---- epilogue ----
#pragma unroll
    for (int mt = 0; mt < 2; ++mt) {
        float inv_lo = 1.0f / lrow[mt][0];
        float inv_hi = 1.0f / lrow[mt][1];
        int row_lo = r0 + wid * 32 + mt * 16 + g;
#pragma unroll
        for (int nt = 0; nt < 8; ++nt) {
            int col = head * WHEAD + nt * 8 + 2 * c;
            float2 lo = make_float2(oacc[mt][nt][0] * inv_lo, oacc[mt][nt][1] * inv_lo);
            float2 hi = make_float2(oacc[mt][nt][2] * inv_hi, oacc[mt][nt][3] * inv_hi);
            *(float2*)&out[(size_t)row_lo * D_MODEL + col] = lo;
            *(float2*)&out[(size_t)(row_lo + 8) * D_MODEL + col] = hi;
        }
    }
}

// ---------------- launch ----------------
extern "C" void kernel_launch(void* const* d_in, const int* in_sizes, int n_in,
                              void* d_out, int out_size)
{
    const float* x    = (const float*)d_in[0];
    const float* mask = (const float*)d_in[1];
    const float* Wq   = (const float*)d_in[2];
    const float* bq   = (const float*)d_in[3];
    float* out = (float*)d_out;

    dim3 gGemm(N_QKV / 64, S_LEN / 128);         // (36, 32)
    qkv_gemm_tc<<<gGemm, 256>>>(x, Wq, bq);

    cudaFuncSetAttribute(attn_tc,
                         cudaFuncAttributeMaxDynamicSharedMemorySize,
                         ATTN_SMEM_BYTES);
    dim3 gAttn(S_LEN / 128, NHEAD);              // (32, 12)
    attn_tc<<<gAttn, 128, ATTN_SMEM_BYTES>>>(mask, out);
}

// round 5
// speedup vs baseline: 4.2729x; 1.1705x over previous
#include <cuda_runtime.h>
#include <cuda_bf16.h>
#include <cstdint>

#define S_LEN 4096
#define D_MODEL 768
#define NHEAD 12
#define WHEAD 64
#define N_QKV 2304

// ---------------- scratch: tf32 bit patterns ----------------
__device__ float g_q[NHEAD * S_LEN * WHEAD];    // [h][s][w]
__device__ float g_kt[NHEAD * WHEAD * S_LEN];   // [h][w][s]  (transposed!)
__device__ float g_v[NHEAD * S_LEN * WHEAD];    // [h][s][w]

// ---------------- helpers ----------------
__device__ __forceinline__ uint32_t f2tf32(float x) {
    uint32_t u;
    asm("cvt.rna.tf32.f32 %0, %1;" : "=r"(u) : "f"(x));
    return u;
}

__device__ __forceinline__ void mma_tf32(
    float& d0, float& d1, float& d2, float& d3,
    uint32_t a0, uint32_t a1, uint32_t a2, uint32_t a3,
    uint32_t b0, uint32_t b1)
{
    asm volatile(
        "mma.sync.aligned.m16n8k8.row.col.f32.tf32.tf32.f32 "
        "{%0,%1,%2,%3},{%4,%5,%6,%7},{%8,%9},{%0,%1,%2,%3};"
        : "+f"(d0), "+f"(d1), "+f"(d2), "+f"(d3)
        : "r"(a0), "r"(a1), "r"(a2), "r"(a3), "r"(b0), "r"(b1));
}

__device__ __forceinline__ void cpa16(void* s, const void* g) {
    uint32_t sa = (uint32_t)__cvta_generic_to_shared(s);
    asm volatile("cp.async.cg.shared.global [%0], [%1], 16;" :: "r"(sa), "l"(g));
}
#define CPA_COMMIT() asm volatile("cp.async.commit_group;" ::: "memory")
#define CPA_WAIT0()  asm volatile("cp.async.wait_group 0;" ::: "memory")

// =============== Kernel 1: QKV GEMM (tf32, cp.async double-buffered) ===============
#define GAP 36   // A pitch (mod 32 == 4)
#define GBP 72   // B pitch (mod 32 == 8)

__global__ __launch_bounds__(256) void qkv_gemm_tc(
    const float* __restrict__ X, const float* __restrict__ Wq,
    const float* __restrict__ bq)
{
    __shared__ float As[2][128 * GAP];
    __shared__ float Bs[2][32 * GBP];

    const int tid = threadIdx.x;
    const int wid = tid >> 5;
    const int lane = tid & 31;
    const int g = lane >> 2;
    const int c = lane & 3;
    const int warp_m = wid >> 1;
    const int warp_n = wid & 1;
    const int m0 = blockIdx.y * 128;
    const int n0 = blockIdx.x * 64;

    float acc[2][4][4];
#pragma unroll
    for (int mt = 0; mt < 2; ++mt)
#pragma unroll
        for (int nt = 0; nt < 4; ++nt)
#pragma unroll
            for (int i = 0; i < 4; ++i) acc[mt][nt][i] = 0.0f;

    const int rowA = tid >> 3, c4A = tid & 7;    // with r offsets
    const int rowB = tid >> 4, c4B = tid & 15;

    auto issue = [&](int k0, int buf) {
#pragma unroll
        for (int r = 0; r < 4; ++r) {
            int row = rowA + r * 32;
            cpa16(&As[buf][row * GAP + c4A * 4],
                  &X[(size_t)(m0 + row) * D_MODEL + k0 + c4A * 4]);
        }
#pragma unroll
        for (int r = 0; r < 2; ++r) {
            int row = rowB + r * 16;
            cpa16(&Bs[buf][row * GBP + c4B * 4],
                  &Wq[(size_t)(k0 + row) * N_QKV + n0 + c4B * 4]);
        }
        CPA_COMMIT();
    };

    issue(0, 0);
    for (int i = 0; i < 24; ++i) {
        CPA_WAIT0();
        __syncthreads();
        if (i + 1 < 24) issue((i + 1) * 32, (i + 1) & 1);
        const float* A = As[i & 1];
        const float* B = Bs[i & 1];
#pragma unroll
        for (int kk = 0; kk < 4; ++kk) {
            uint32_t af[2][4];
#pragma unroll
            for (int mt = 0; mt < 2; ++mt) {
                int mr = warp_m * 32 + mt * 16 + g;
                af[mt][0] = f2tf32(A[mr * GAP + kk * 8 + c]);
                af[mt][1] = f2tf32(A[(mr + 8) * GAP + kk * 8 + c]);
                af[mt][2] = f2tf32(A[mr * GAP + kk * 8 + c + 4]);
                af[mt][3] = f2tf32(A[(mr + 8) * GAP + kk * 8 + c + 4]);
            }
#pragma unroll
            for (int nt = 0; nt < 4; ++nt) {
                int nc = warp_n * 32 + nt * 8 + g;
                uint32_t b0 = f2tf32(B[(kk * 8 + c) * GBP + nc]);
                uint32_t b1 = f2tf32(B[(kk * 8 + c + 4) * GBP + nc]);
#pragma unroll
                for (int mt = 0; mt < 2; ++mt)
                    mma_tf32(acc[mt][nt][0], acc[mt][nt][1], acc[mt][nt][2], acc[mt][nt][3],
                             af[mt][0], af[mt][1], af[mt][2], af[mt][3], b0, b1);
            }
        }
        __syncthreads();
    }

    // epilogue: bias, convert to tf32 bits, scatter (K transposed)
    const int sel = n0 / D_MODEL;
    const int head = (n0 % D_MODEL) / WHEAD;

#pragma unroll
    for (int mt = 0; mt < 2; ++mt) {
#pragma unroll
        for (int nt = 0; nt < 4; ++nt) {
            int w = warp_n * 32 + nt * 8 + 2 * c;
            float b0 = bq[n0 + w], b1 = bq[n0 + w + 1];
            int m_lo = m0 + warp_m * 32 + mt * 16 + g;
            float v00 = __uint_as_float(f2tf32(acc[mt][nt][0] + b0));
            float v01 = __uint_as_float(f2tf32(acc[mt][nt][1] + b1));
            float v10 = __uint_as_float(f2tf32(acc[mt][nt][2] + b0));
            float v11 = __uint_as_float(f2tf32(acc[mt][nt][3] + b1));
            if (sel == 1) {   // K: [h][w][s]
                float* kt = g_kt + (size_t)head * WHEAD * S_LEN;
                kt[(size_t)w * S_LEN + m_lo] = v00;
                kt[(size_t)(w + 1) * S_LEN + m_lo] = v01;
                kt[(size_t)w * S_LEN + m_lo + 8] = v10;
                kt[(size_t)(w + 1) * S_LEN + m_lo + 8] = v11;
            } else {
                float* dst = (sel == 0) ? g_q : g_v;
                *(float2*)&dst[((size_t)head * S_LEN + m_lo) * WHEAD + w] = make_float2(v00, v01);
                *(float2*)&dst[((size_t)head * S_LEN + m_lo + 8) * WHEAD + w] = make_float2(v10, v11);
            }
        }
    }
}

// =============== Kernel 2: flash attention (tf32, cp.async pipelined) ===============
#define QPITCH 68   // mod 32 == 4
#define KPITCH 72   // mod 32 == 8
#define VPITCH 72
#define SM_Q   0
#define SM_K   (128 * QPITCH)
#define SM_V   (SM_K + 64 * KPITCH)
#define SM_AM  (SM_V + 64 * VPITCH)
#define ATTN_SMEM_U32 (SM_AM + 2 * 64)
#define ATTN_SMEM_BYTES (ATTN_SMEM_U32 * 4)   // ~72 KB

#define LOG2E 1.4426950408889634f
#define SCL   (0.125f * LOG2E)
#define AMC   (10000.0f * LOG2E)

__global__ __launch_bounds__(128, 3) void attn_tc(
    const float* __restrict__ mask, float* __restrict__ out)
{
    extern __shared__ uint32_t sm[];
    float* smf = (float*)sm;

    const int tid = threadIdx.x;
    const int wid = tid >> 5;
    const int lane = tid & 31;
    const int g = lane >> 2;
    const int c = lane & 3;
    const int srcA = (lane & 28) | (c >> 1);
    const int srcB = srcA + 2;
    const int r0 = blockIdx.x * 128;
    const int head = blockIdx.y;

    const float* qh = g_q + (size_t)head * S_LEN * WHEAD;
    const float* kt = g_kt + (size_t)head * WHEAD * S_LEN;
    const float* vh = g_v + (size_t)head * S_LEN * WHEAD;

    const int rowL = tid >> 4, c4L = tid & 15;   // 128-thread tile mapping

    // ---- prologue: async-copy Q (128x64), K(0), V(0), mask(0) ----
#pragma unroll
    for (int r = 0; r < 16; ++r) {
        int row = rowL + r * 8;
        cpa16(&sm[SM_Q + row * QPITCH + c4L * 4],
              &qh[(size_t)(r0 + row) * WHEAD + c4L * 4]);
    }
#pragma unroll
    for (int r = 0; r < 8; ++r) {
        int w = rowL + r * 8;
        cpa16(&sm[SM_K + w * KPITCH + c4L * 4], &kt[(size_t)w * S_LEN + c4L * 4]);
        cpa16(&sm[SM_V + w * VPITCH + c4L * 4], &vh[(size_t)w * WHEAD + c4L * 4]);
    }
    if (tid < 16) cpa16(&sm[SM_AM + tid * 4], &mask[tid * 4]);
    CPA_COMMIT();

    float oacc[2][8][4];
#pragma unroll
    for (int mt = 0; mt < 2; ++mt)
#pragma unroll
        for (int nt = 0; nt < 8; ++nt)
#pragma unroll
            for (int i = 0; i < 4; ++i) oacc[mt][nt][i] = 0.0f;
    float mrow[2][2], lrow[2][2];
#pragma unroll
    for (int mt = 0; mt < 2; ++mt) {
        mrow[mt][0] = mrow[mt][1] = -1e30f;
        lrow[mt][0] = lrow[mt][1] = 0.0f;
    }

    CPA_WAIT0();
    __syncthreads();

    for (int t = 0; t < S_LEN / 64; ++t) {
        // ---- S = Q K^T : 32 rows x 64 cols per warp ----
        float sacc[2][8][4];
#pragma unroll
        for (int mt = 0; mt < 2; ++mt)
#pragma unroll
            for (int nt = 0; nt < 8; ++nt)
#pragma unroll
                for (int i = 0; i < 4; ++i) sacc[mt][nt][i] = 0.0f;

#pragma unroll
        for (int kk = 0; kk < 8; ++kk) {
            uint32_t af[2][4];
#pragma unroll
            for (int mt = 0; mt < 2; ++mt) {
                int mr = wid * 32 + mt * 16 + g;
                af[mt][0] = sm[SM_Q + mr * QPITCH + kk * 8 + c];
                af[mt][1] = sm[SM_Q + (mr + 8) * QPITCH + kk * 8 + c];
                af[mt][2] = sm[SM_Q + mr * QPITCH + kk * 8 + c + 4];
                af[mt][3] = sm[SM_Q + (mr + 8) * QPITCH + kk * 8 + c + 4];
            }
#pragma unroll
            for (int nt = 0; nt < 8; ++nt) {
                uint32_t b0 = sm[SM_K + (kk * 8 + c) * KPITCH + nt * 8 + g];
                uint32_t b1 = sm[SM_K + (kk * 8 + c + 4) * KPITCH + nt * 8 + g];
#pragma unroll
                for (int mt = 0; mt < 2; ++mt)
                    mma_tf32(sacc[mt][nt][0], sacc[mt][nt][1], sacc[mt][nt][2], sacc[mt][nt][3],
                             af[mt][0], af[mt][1], af[mt][2], af[mt][3], b0, b1);
            }
        }

        __syncthreads();   // all warps done reading K
        // ---- prefetch K(t+1) + mask(t+1) (overlaps softmax + PV) ----
        if (t + 1 < S_LEN / 64) {
            const int t1 = (t + 1) * 64;
#pragma unroll
            for (int r = 0; r < 8; ++r) {
                int w = rowL + r * 8;
                cpa16(&sm[SM_K + w * KPITCH + c4L * 4], &kt[(size_t)w * S_LEN + t1 + c4L * 4]);
            }
            if (tid < 16) cpa16(&sm[SM_AM + ((t + 1) & 1) * 64 + tid * 4], &mask[t1 + tid * 4]);
        }
        CPA_COMMIT();

        // ---- additive mask (log2 domain) ----
        float amv[8][2];
#pragma unroll
        for (int nt = 0; nt < 8; ++nt) {
            float m0v = smf[SM_AM + (t & 1) * 64 + nt * 8 + 2 * c];
            float m1v = smf[SM_AM + (t & 1) * 64 + nt * 8 + 2 * c + 1];
            amv[nt][0] = fmaf(m0v, AMC, -AMC);
            amv[nt][1] = fmaf(m1v, AMC, -AMC);
        }

        // ---- online softmax per m-tile (log2 domain) ----
#pragma unroll
        for (int mt = 0; mt < 2; ++mt) {
            float vmax_lo = -1e30f, vmax_hi = -1e30f;
#pragma unroll
            for (int nt = 0; nt < 8; ++nt) {
                sacc[mt][nt][0] = fmaf(sacc[mt][nt][0], SCL, amv[nt][0]);
                sacc[mt][nt][1] = fmaf(sacc[mt][nt][1], SCL, amv[nt][1]);
                sacc[mt][nt][2] = fmaf(sacc[mt][nt][2], SCL, amv[nt][0]);
                sacc[mt][nt][3] = fmaf(sacc[mt][nt][3], SCL, amv[nt][1]);
                vmax_lo = fmaxf(vmax_lo, fmaxf(sacc[mt][nt][0], sacc[mt][nt][1]));
                vmax_hi = fmaxf(vmax_hi, fmaxf(sacc[mt][nt][2], sacc[mt][nt][3]));
            }
#pragma unroll
            for (int off = 1; off <= 2; off <<= 1) {
                vmax_lo = fmaxf(vmax_lo, __shfl_xor_sync(0xffffffffu, vmax_lo, off));
                vmax_hi = fmaxf(vmax_hi, __shfl_xor_sync(0xffffffffu, vmax_hi, off));
            }
            float mn_lo = fmaxf(mrow[mt][0], vmax_lo);
            float mn_hi = fmaxf(mrow[mt][1], vmax_hi);
            float corr_lo = exp2f(mrow[mt][0] - mn_lo);
            float corr_hi = exp2f(mrow[mt][1] - mn_hi);
            float rs_lo = 0.0f, rs_hi = 0.0f;
#pragma unroll
            for (int nt = 0; nt < 8; ++nt) {
                sacc[mt][nt][0] = exp2f(sacc[mt][nt][0] - mn_lo);
                sacc[mt][nt][1] = exp2f(sacc[mt][nt][1] - mn_lo);
                sacc[mt][nt][2] = exp2f(sacc[mt][nt][2] - mn_hi);
                sacc[mt][nt][3] = exp2f(sacc[mt][nt][3] - mn_hi);
                rs_lo += sacc[mt][nt][0] + sacc[mt][nt][1];
                rs_hi += sacc[mt][nt][2] + sacc[mt][nt][3];
            }
#pragma unroll
            for (int off = 1; off <= 2; off <<= 1) {
                rs_lo += __shfl_xor_sync(0xffffffffu, rs_lo, off);
                rs_hi += __shfl_xor_sync(0xffffffffu, rs_hi, off);
            }
            lrow[mt][0] = lrow[mt][0] * corr_lo + rs_lo;
            lrow[mt][1] = lrow[mt][1] * corr_hi + rs_hi;
            mrow[mt][0] = mn_lo; mrow[mt][1] = mn_hi;
#pragma unroll
            for (int nt = 0; nt < 8; ++nt) {
                oacc[mt][nt][0] *= corr_lo; oacc[mt][nt][1] *= corr_lo;
                oacc[mt][nt][2] *= corr_hi; oacc[mt][nt][3] *= corr_hi;
            }
        }

        // ---- P to tf32 in registers ----
        uint32_t su[2][8][4];
#pragma unroll
        for (int mt = 0; mt < 2; ++mt)
#pragma unroll
            for (int nt = 0; nt < 8; ++nt)
#pragma unroll
                for (int i = 0; i < 4; ++i)
                    su[mt][nt][i] = f2tf32(sacc[mt][nt][i]);

        // ---- O += P V ; A-frags via intra-quad shuffles ----
#pragma unroll
        for (int kk = 0; kk < 8; ++kk) {
            uint32_t af[2][4];
#pragma unroll
            for (int mt = 0; mt < 2; ++mt) {
                uint32_t p0 = su[mt][kk][0], p1 = su[mt][kk][1];
                uint32_t p2 = su[mt][kk][2], p3 = su[mt][kk][3];
                uint32_t x0 = __shfl_sync(0xffffffffu, p0, srcA);
                uint32_t x1 = __shfl_sync(0xffffffffu, p1, srcA);
                uint32_t y0 = __shfl_sync(0xffffffffu, p0, srcB);
                uint32_t y1 = __shfl_sync(0xffffffffu, p1, srcB);
                af[mt][0] = (c & 1) ? x1 : x0;
                af[mt][2] = (c & 1) ? y1 : y0;
                uint32_t x2 = __shfl_sync(0xffffffffu, p2, srcA);
                uint32_t x3 = __shfl_sync(0xffffffffu, p3, srcA);
                uint32_t y2 = __shfl_sync(0xffffffffu, p2, srcB);
                uint32_t y3 = __shfl_sync(0xffffffffu, p3, srcB);
                af[mt][1] = (c & 1) ? x3 : x2;
                af[mt][3] = (c & 1) ? y3 : y2;
            }
#pragma unroll
            for (int nt = 0; nt < 8; ++nt) {
                uint32_t b0 = sm[SM_V + (kk * 8 + c) * VPITCH + nt * 8 + g];
                uint32_t b1 = sm[SM_V + (kk * 8 + c + 4) * VPITCH + nt * 8 + g];
#pragma unroll
                for (int mt = 0; mt < 2; ++mt)
                    mma_tf32(oacc[mt][nt][0], oacc[mt][nt][1], oacc[mt][nt][2], oacc[mt][nt][3],
                             af[mt][0], af[mt][1], af[mt][2], af[mt][3], b0, b1);
            }
        }

        __syncthreads();   // all warps done reading V
        // ---- prefetch V(t+1) ----
        if (t + 1 < S_LEN / 64) {
            const int t1 = (t + 1) * 64;
#pragma unroll
            for (int r = 0; r < 8; ++r) {
                int j = rowL + r * 8;
                cpa16(&sm[SM_V + j * VPITCH + c4L * 4],
                      &vh[(size_t)(t1 + j) * WHEAD + c4L * 4]);
            }
        }
        CPA_COMMIT();
        CPA_WAIT0();
        __syncthreads();
    }

    // ---- epilogue ----
#pragma unroll
    for (int mt = 0; mt < 2; ++mt) {
        float inv_lo = 1.0f / lrow[mt][0];
        float inv_hi = 1.0f / lrow[mt][1];
        int row_lo = r0 + wid * 32 + mt * 16 + g;
#pragma unroll
        for (int nt = 0; nt < 8; ++nt) {
            int col = head * WHEAD + nt * 8 + 2 * c;
            float2 lo = make_float2(oacc[mt][nt][0] * inv_lo, oacc[mt][nt][1] * inv_lo);
            float2 hi = make_float2(oacc[mt][nt][2] * inv_hi, oacc[mt][nt][3] * inv_hi);
            *(float2*)&out[(size_t)row_lo * D_MODEL + col] = lo;
            *(float2*)&out[(size_t)(row_lo + 8) * D_MODEL + col] = hi;
        }
    }
}

// ---------------- launch ----------------
extern "C" void kernel_launch(void* const* d_in, const int* in_sizes, int n_in,
                              void* d_out, int out_size)
{
    const float* x    = (const float*)d_in[0];
    const float* mask = (const float*)d_in[1];
    const float* Wq   = (const float*)d_in[2];
    const float* bq   = (const float*)d_in[3];
    float* out = (float*)d_out;

    dim3 gGemm(N_QKV / 64, S_LEN / 128);         // (36, 32)
    qkv_gemm_tc<<<gGemm, 256>>>(x, Wq, bq);

    cudaFuncSetAttribute(attn_tc,
                         cudaFuncAttributeMaxDynamicSharedMemorySize,
                         ATTN_SMEM_BYTES);
    dim3 gAttn(S_LEN / 128, NHEAD);              // (32, 12)
    attn_tc<<<gAttn, 128, ATTN_SMEM_BYTES>>>(mask, out);
}